// round 7
// baseline (speedup 1.0000x reference)
#include <cuda_runtime.h>
#include <math.h>

#define TT    1460
#define GG    5000
#define TS    30              // timesteps per smem tile (2 x 15-chunk)
#define NT    49              // ceil(1460/30)
#define CPW   64              // cells per warp (2 per thread)
#define ROWF2 192             // 64 cells * 3 floats per timestep row
#define CH    15              // UH length
#define NSL   14              // conv t-slices
#define SLEN  105             // steps per conv slice (7 * 15)

// scratch: (ht0, ht1, gw, pad) per (t, g) -- 116.8 MB
__device__ float4 g_scr[(size_t)TT * GG];

// ---- packed f32x2 + approx transcendental helpers -----------------------------
#define PACK2(d, lo, hi)   asm("mov.b64 %0, {%1, %2};" : "=l"(d) : "f"(lo), "f"(hi))
#define UNPACK2(lo, hi, d) asm("mov.b64 {%0, %1}, %2;" : "=f"(lo), "=f"(hi) : "l"(d))
#define FMA2(d, a, b, c)   asm("fma.rn.f32x2 %0, %1, %2, %3;" : "=l"(d) : "l"(a), "l"(b), "l"(c))

__device__ __forceinline__ float lg2a(float x) { float r; asm("lg2.approx.f32 %0, %1;" : "=f"(r) : "f"(x)); return r; }
__device__ __forceinline__ float ex2a(float x) { float r; asm("ex2.approx.f32 %0, %1;" : "=f"(r) : "f"(x)); return r; }

__device__ __forceinline__ void cp_async16(void* sm, const void* gm) {
    unsigned a = (unsigned)__cvta_generic_to_shared(sm);
    asm volatile("cp.async.cg.shared.global [%0], [%1], 16;\n" :: "r"(a), "l"(gm));
}
__device__ __forceinline__ void cp_commit() { asm volatile("cp.async.commit_group;\n" ::: "memory"); }
__device__ __forceinline__ void cp_wait1()  { asm volatile("cp.async.wait_group 1;\n" ::: "memory"); }
__device__ __forceinline__ void cp_wait0()  { asm volatile("cp.async.wait_group 0;\n" ::: "memory"); }

// =============================== Kernel A: dual-chain scan ======================
__global__ __launch_bounds__(32, 1)
void hmets_scan(const float* __restrict__ x,
                const float* __restrict__ par)
{
    __shared__ float sm[2 * TS * ROWF2];   // 46080 B double buffered
    const int lane = threadIdx.x;
    const int g0   = blockIdx.x * CPW;
    const bool fullblk = (g0 + CPW <= GG);

    int  gc[2];  bool act[2];
    gc[0] = g0 + lane;        act[0] = (gc[0] < GG);
    gc[1] = g0 + 32 + lane;   act[1] = (gc[1] < GG);

    // -------- per-cell parameters, 2 cells per thread -------------------------------
    float ddf_min[2], ddf_sum[2], Tbm[2], fcmin[2], fc_sum[2], Tbf[2], Kf[2], efe[2];
    float ETe[2], cRun[2], cV2P[2], cVad[2], cPh[2], Vmax[2], invVmax[2];
    float dmK[2], fcC[2], cVb[2];
#pragma unroll
    for (int c = 0; c < 2; c++) {
        const float* pr = par + ((size_t)(TT - 1) * GG + (act[c] ? gc[c] : (GG - 1))) * 20;
        float s[16];
#pragma unroll
        for (int i = 0; i < 16; i++) {
            float v = __ldg(pr + i);
            s[i] = 1.0f / (1.0f + expf(-v));
        }
        ddf_min[c] = 20.0f * s[0];
        ddf_sum[c] = ddf_min[c] + 20.0f * s[1];
        Tbm[c]     = -2.0f + 5.0f * s[2];
        float Kcum = 0.01f + 0.19f * s[3];
        fcmin[c]   = 0.1f * s[4];
        fc_sum[c]  = fcmin[c] + 0.01f + 0.24f * s[5];
        float Ccum = 0.005f + 0.045f * s[6];
        Tbf[c]     = -5.0f + 7.0f * s[7];
        Kf[c]      = 5.0f * s[8];
        efe[c]     = s[9];
        ETe[c]     = 3.0f * s[10];
        cRun[c]    = s[11];
        cV2P[c]    = 1e-5f + (0.02f - 1e-5f) * s[12];
        cVad[c]    = 0.1f * s[13];
        cPh[c]     = 1e-5f + (0.01f - 1e-5f) * s[14];
        Vmax[c]    = 0.001f + (500.0f - 0.001f) * s[15];
        invVmax[c] = 1.0f / Vmax[c];
        dmK[c]     = ddf_min[c] * Kcum;
        fcC[c]     = fc_sum[c] * Ccum;
        cVb[c]     = 1.0f - cVad[c] - cV2P[c];
    }

    // -------- forcing tile prefetch (cp.async, zero-padded) -------------------------
    auto prefetch = [&](int k) {
        float* dst = sm + (k & 1) * (TS * ROWF2);
        int t0 = k * TS;
        if (fullblk) {
            for (int j = lane; j < TS * 48; j += 32) {       // 48 float4 per row
                int row = j / 48, c = j - row * 48;
                if (t0 + row < TT) {
                    const float* gp = x + (size_t)(t0 + row) * (GG * 3) + g0 * 3 + c * 4;
                    cp_async16(dst + row * ROWF2 + c * 4, gp);
                } else {
                    float4 z = {0.f, 0.f, 0.f, 0.f};
                    *(float4*)(dst + row * ROWF2 + c * 4) = z;
                }
            }
        } else {
            for (int j = lane; j < TS * ROWF2; j += 32) {
                int row = j / ROWF2, c = j - row * ROWF2;
                int cell = g0 + c / 3;
                dst[row * ROWF2 + c] = (cell < GG && t0 + row < TT)
                    ? __ldg(x + (size_t)(t0 + row) * (GG * 3) + g0 * 3 + c) : 0.0f;
            }
        }
        cp_commit();
    };

    // -------- state (2 independent chains) ------------------------------------------
    float S[2], W[2], Cc[2], V[2], Pz[2];
#pragma unroll
    for (int c = 0; c < 2; c++) {
        S[c] = 1e-5f; W[c] = 1e-5f; Cc[c] = 1e-5f; Pz[c] = 1e-5f;
        V[c] = 0.5f * Vmax[c];
    }

    prefetch(0);
    for (int k = 0; k < NT; k++) {
        const int t0 = k * TS;
        if (k + 1 < NT) { prefetch(k + 1); cp_wait1(); }
        else            { cp_wait0(); }
        __syncwarp();
        const float* sb = sm + (k & 1) * (TS * ROWF2);

#pragma unroll 1
        for (int c2 = 0; c2 < 2; c2++) {
            const int tb = t0 + c2 * CH;
            const float* rb = sb + c2 * CH * ROWF2;

#pragma unroll
            for (int u = 0; u < CH; u++) {
                const int t = tb + u;
#pragma unroll
                for (int c = 0; c < 2; c++) {                  // two independent spines
                    const float* rp = rb + u * ROWF2 + (lane + 32 * c) * 3;
                    float Pp = rp[0];
                    float Tt = rp[1];
                    float PE = rp[2];

                    float rain = (Tt >= 0.0f) ? Pp : 0.0f;
                    float snow = Pp - rain;
                    float base = fmaxf(Tbf[c] - Tt, 1e-5f);
                    float potf = Kf[c] * ex2a(efe[c] * lg2a(base));
                    float dtp  = fmaxf(Tt - Tbm[c], 0.0f);

                    // snowpack
                    float fr = fminf(potf, W[c]);
                    W[c] -= fr;
                    S[c] += fr;
                    float ddf  = fminf(fmaf(dmK[c], Cc[c], ddf_min[c]), ddf_sum[c]);
                    float S1   = S[c] + snow;
                    float melt = fminf(ddf * dtp, S1);
                    S[c] = S1 - melt;
                    float Ct = Cc[c] + melt;
                    Cc[c] = (S[c] > 1e-5f) ? Ct : 0.0f;

                    // retention
                    float wrf  = fmaxf(fmaf(-fcC[c], Cc[c], fc_sum[c]), fcmin[c]);
                    float wr   = wrf * S[c];
                    float wtmp = (W[c] + rain) + melt;
                    float wa   = fmaxf(wtmp - wr, 0.0f);
                    W[c] = (wa > 0.0f) ? wr : wtmp;

                    // vadose / phreatic
                    float RET   = ETe[c] * PE;
                    float ratio = V[c] * invVmax[c];
                    float cr    = cRun[c] * ratio;
                    float cr2   = cr * ratio;
                    float ht0   = cr * wa;
                    float infil = fmaxf((wa - RET) - ht0, 0.0f);
                    float ht1   = cr2 * infil;
                    float ht2   = cVad[c] * V[c];
                    float v2p   = cV2P[c] * V[c];
                    float Vb    = fmaf(cVb[c], V[c], infil);
                    V[c] = Vb - ht1;
                    float over = fmaxf(V[c] - Vmax[c], 0.0f);
                    V[c] -= over;
                    ht1 += over;
                    float Pp1 = Pz[c] + v2p;
                    float ht3 = cPh[c] * Pp1;
                    Pz[c] = Pp1 - ht3;

                    if (act[c] && t < TT) {
                        float4 h; h.x = ht0; h.y = ht1; h.z = ht2 + ht3; h.w = 0.0f;
                        g_scr[(size_t)t * GG + gc[c]] = h;     // STG.128, coalesced
                    }
                }
            }
        }
        __syncwarp();
    }
}

// ============================ Kernel B: dual gamma-UH conv ======================
// grid (157, 14), block 32. Each thread: one cell, one 105-step t-slice.
__global__ __launch_bounds__(32, 16)
void hmets_conv(const float* __restrict__ par,
                float* __restrict__ out)
{
    const int lane = threadIdx.x;
    const int g    = blockIdx.x * 32 + lane;
    if (g >= GG) return;
    const int t0   = blockIdx.y * SLEN;

    // routing params (sigmoid of last row, cols 16..19)
    const float* pr = par + ((size_t)(TT - 1) * GG + g) * 20 + 16;
    float a1 = 0.3f  + (20.0f - 0.3f)  / (1.0f + expf(-__ldg(pr + 0)));
    float b1 = 0.01f + (5.0f  - 0.01f) / (1.0f + expf(-__ldg(pr + 1)));
    float a2 = 0.5f  + (13.0f - 0.5f)  / (1.0f + expf(-__ldg(pr + 2)));
    float b2 = 0.15f + (1.5f  - 0.15f) / (1.0f + expf(-__ldg(pr + 3)));

    unsigned long long uhp[CH];
    {
        const float L2E = 1.44269504f;
        float i1 = L2E / b1, i2 = L2E / b2;
        float w1[CH], w2[CH];
        float n1 = 0.f, n2 = 0.f;
#pragma unroll
        for (int l = 0; l < CH; l++) {
            float t  = (float)l + 0.5f;
            float lt = lg2a(t);
            w1[l] = ex2a(fmaf(a1 - 1.0f, lt, -t * i1));
            w2[l] = ex2a(fmaf(a2 - 1.0f, lt, -t * i2));
            n1 += w1[l]; n2 += w2[l];
        }
        n1 = 1.0f / n1; n2 = 1.0f / n2;
#pragma unroll
        for (int l = 0; l < CH; l++) PACK2(uhp[l], w1[l] * n1, w2[l] * n2);
    }

    // ring preload: slot j holds h[t0 - 15 + j]  (t mod 15 == j)
    unsigned long long hpk[CH];
    hpk[0] = 0ull;
#pragma unroll
    for (int j = 1; j < CH; j++) {
        int t = t0 - CH + j;
        if (t >= 0) {
            float4 h = __ldg(&g_scr[(size_t)t * GG + g]);
            PACK2(hpk[j], h.x, h.y);
        } else hpk[j] = 0ull;
    }

#pragma unroll 1
    for (int cb = 0; cb < SLEN / CH; cb++) {
        const int tb = t0 + cb * CH;
        if (tb >= TT) break;

        // batch-load 15 history rows (MLP=15)
        float4 hv[CH];
#pragma unroll
        for (int u = 0; u < CH; u++) {
            int t = tb + u;
            hv[u] = (t < TT) ? __ldg(&g_scr[(size_t)t * GG + g])
                             : make_float4(0.f, 0.f, 0.f, 0.f);
        }
#pragma unroll
        for (int u = 0; u < CH; u++) {
            PACK2(hpk[u], hv[u].x, hv[u].y);
            unsigned long long qp = 0ull;
#pragma unroll
            for (int l = 0; l < CH; l++)
                FMA2(qp, uhp[l], hpk[(u - l + CH) % CH], qp);
            float qlo, qhi;
            UNPACK2(qlo, qhi, qp);
            if (tb + u < TT)
                out[(size_t)(tb + u) * GG + g] = hv[u].z + qlo + qhi;
        }
    }
}

extern "C" void kernel_launch(void* const* d_in, const int* in_sizes, int n_in,
                              void* d_out, int out_size)
{
    (void)in_sizes; (void)n_in; (void)out_size;
    const float* x   = (const float*)d_in[0];   // x_phy  [1460, 5000, 3]
    const float* par = (const float*)d_in[1];   // params [1460, 5000, 20]
    float* out = (float*)d_out;                 // Q      [1460, 5000]

    hmets_scan<<<(GG + CPW - 1) / CPW, 32>>>(x, par);
    dim3 cg((GG + 31) / 32, NSL);
    hmets_conv<<<cg, 32>>>(par, out);
}

// round 8
// speedup vs baseline: 1.4827x; 1.4827x over previous
#include <cuda_runtime.h>
#include <math.h>

#define TT    1460
#define TTP   1470            // padded T (49 * 30), scratch rows beyond TT are junk
#define GG    5000
#define TS    30              // timesteps per smem tile (2 x 15-chunk)
#define NT    49              // 1470 / 30, all tiles full
#define ROWF  96              // 32 cells * 3 floats per timestep row
#define CH    15              // UH length
#define NSL   14              // conv t-slices
#define SLEN  105             // steps per conv slice (7 * 15)

// scratch: (ht0, ht1, gw, pad) per (t, g), padded T + dummy slots for inactive lanes
__device__ float4 g_scr[(size_t)TTP * GG + 32];

// ---- packed f32x2 + approx transcendental helpers -----------------------------
#define PACK2(d, lo, hi)   asm("mov.b64 %0, {%1, %2};" : "=l"(d) : "f"(lo), "f"(hi))
#define UNPACK2(lo, hi, d) asm("mov.b64 {%0, %1}, %2;" : "=f"(lo), "=f"(hi) : "l"(d))
#define FMA2(d, a, b, c)   asm("fma.rn.f32x2 %0, %1, %2, %3;" : "=l"(d) : "l"(a), "l"(b), "l"(c))

__device__ __forceinline__ float lg2a(float x) { float r; asm("lg2.approx.f32 %0, %1;" : "=f"(r) : "f"(x)); return r; }
__device__ __forceinline__ float ex2a(float x) { float r; asm("ex2.approx.f32 %0, %1;" : "=f"(r) : "f"(x)); return r; }

__device__ __forceinline__ void cp_async16(void* sm, const void* gm) {
    unsigned a = (unsigned)__cvta_generic_to_shared(sm);
    asm volatile("cp.async.cg.shared.global [%0], [%1], 16;\n" :: "r"(a), "l"(gm));
}
__device__ __forceinline__ void cp_commit() { asm volatile("cp.async.commit_group;\n" ::: "memory"); }
__device__ __forceinline__ void cp_wait1()  { asm volatile("cp.async.wait_group 1;\n" ::: "memory"); }
__device__ __forceinline__ void cp_wait0()  { asm volatile("cp.async.wait_group 0;\n" ::: "memory"); }

// =============================== Kernel A: scan (spine only) ====================
__global__ __launch_bounds__(32, 1)
void hmets_scan(const float* __restrict__ x,
                const float* __restrict__ par)
{
    __shared__ float sm[2 * TS * ROWF];   // 23040 B double buffered
    const int lane = threadIdx.x;
    const int g0   = blockIdx.x * 32;
    const int g    = g0 + lane;
    const bool active  = (g < GG);
    const bool fullblk = (g0 + 32 <= GG);

    // -------- per-cell physical parameters (last timestep row only) -----------------
    const float* pr = par + ((size_t)(TT - 1) * GG + (active ? g : (GG - 1))) * 20;
    float s[16];
#pragma unroll
    for (int i = 0; i < 16; i++) {
        float v = __ldg(pr + i);
        s[i] = 1.0f / (1.0f + expf(-v));
    }
    const float ddf_min = 20.0f * s[0];
    const float ddf_sum = ddf_min + 20.0f * s[1];
    const float Tbm     = -2.0f + 5.0f * s[2];
    const float Kcum    = 0.01f + 0.19f * s[3];
    const float fcmin   = 0.1f * s[4];
    const float fc_sum  = fcmin + 0.01f + 0.24f * s[5];
    const float Ccum    = 0.005f + 0.045f * s[6];
    const float Tbf     = -5.0f + 7.0f * s[7];
    const float Kf      = 5.0f * s[8];
    const float efe     = s[9];
    const float ETe     = 3.0f * s[10];
    const float cRun    = s[11];
    const float cV2P    = 1e-5f + (0.02f - 1e-5f) * s[12];
    const float cVad    = 0.1f * s[13];
    const float cPh     = 1e-5f + (0.01f - 1e-5f) * s[14];
    const float Vmax    = 0.001f + (500.0f - 0.001f) * s[15];
    const float invVmax = 1.0f / Vmax;
    const float dmK  = ddf_min * Kcum;       // ddf = fma(dmK, C, ddf_min)
    const float fcC  = fc_sum * Ccum;        // wrf = fma(-fcC, C, fc_sum)
    const float cVb  = 1.0f - cVad - cV2P;   // V' = fma(cVb, V, infil) - ht1

    // -------- forcing tile prefetch (cp.async, zero-padded beyond TT) ---------------
    auto prefetch = [&](int k) {
        float* dst = sm + (k & 1) * (TS * ROWF);
        int t0 = k * TS;
        if (fullblk) {
            for (int j = lane; j < TS * 24; j += 32) {       // 24 float4 per row
                int row = j / 24, c = j - row * 24;
                if (t0 + row < TT) {
                    const float* gp = x + (size_t)(t0 + row) * (GG * 3) + g0 * 3 + c * 4;
                    cp_async16(dst + row * ROWF + c * 4, gp);
                } else {
                    float4 z = {0.f, 0.f, 0.f, 0.f};
                    *(float4*)(dst + row * ROWF + c * 4) = z;
                }
            }
        } else {
            for (int j = lane; j < TS * ROWF; j += 32) {
                int row = j / ROWF, c = j - row * ROWF;
                int cell = g0 + c / 3;
                dst[row * ROWF + c] = (cell < GG && t0 + row < TT)
                    ? __ldg(x + (size_t)(t0 + row) * (GG * 3) + g0 * 3 + c) : 0.0f;
            }
        }
        cp_commit();
    };

    // -------- state -----------------------------------------------------------------
    float S = 1e-5f, W = 1e-5f, C = 1e-5f, P = 1e-5f;
    float V = 0.5f * Vmax;

    // unguarded store path: inactive lanes park on a private dummy slot (stride 0)
    float4*      sp    = active ? (g_scr + g) : (g_scr + (size_t)TTP * GG + lane);
    const size_t sstep = active ? (size_t)GG : 0;

    prefetch(0);
    for (int k = 0; k < NT; k++) {                 // all 49 tiles are full (padded)
        if (k + 1 < NT) { prefetch(k + 1); cp_wait1(); }
        else            { cp_wait0(); }
        __syncwarp();
        const float* sb = sm + (k & 1) * (TS * ROWF);

#pragma unroll 1
        for (int c2 = 0; c2 < 2; c2++) {
            const float* rb = sb + c2 * CH * ROWF + lane * 3;
#pragma unroll
            for (int u = 0; u < CH; u++) {
                float Pp = rb[u * ROWF + 0];
                float Tt = rb[u * ROWF + 1];
                float PE = rb[u * ROWF + 2];

                float rain = (Tt >= 0.0f) ? Pp : 0.0f;
                float snow = Pp - rain;
                float base = fmaxf(Tbf - Tt, 1e-5f);
                float potf = Kf * ex2a(efe * lg2a(base));
                float dtp  = fmaxf(Tt - Tbm, 0.0f);

                // snowpack
                float fr = fminf(potf, W);
                W -= fr;
                S += fr;
                float ddf  = fminf(fmaf(dmK, C, ddf_min), ddf_sum);
                float S1   = S + snow;
                float melt = fminf(ddf * dtp, S1);
                S = S1 - melt;
                float Ct = C + melt;
                C = (S > 1e-5f) ? Ct : 0.0f;

                // retention
                float wrf  = fmaxf(fmaf(-fcC, C, fc_sum), fcmin);
                float wr   = wrf * S;
                float wtmp = (W + rain) + melt;
                float wa   = fmaxf(wtmp - wr, 0.0f);
                W = (wa > 0.0f) ? wr : wtmp;

                // vadose / phreatic
                float RET   = ETe * PE;
                float ratio = V * invVmax;
                float cr    = cRun * ratio;
                float cr2   = cr * ratio;
                float ht0   = cr * wa;
                float infil = fmaxf((wa - RET) - ht0, 0.0f);
                float ht1   = cr2 * infil;
                float ht2   = cVad * V;
                float v2p   = cV2P * V;
                float Vb    = fmaf(cVb, V, infil);
                V = Vb - ht1;
                float over = fmaxf(V - Vmax, 0.0f);
                V -= over;
                ht1 += over;
                float Pp1 = P + v2p;
                float ht3 = cPh * Pp1;
                P = Pp1 - ht3;

                // one unguarded STG.128, pointer-increment addressing
                float4 h; h.x = ht0; h.y = ht1; h.z = ht2 + ht3; h.w = 0.0f;
                *sp = h;
                sp += sstep;
            }
        }
        __syncwarp();
    }
}

// ============================ Kernel B: dual gamma-UH conv ======================
// grid (157, 14), block 32. Each thread: one cell, one 105-step t-slice.
__global__ __launch_bounds__(32, 16)
void hmets_conv(const float* __restrict__ par,
                float* __restrict__ out)
{
    const int lane = threadIdx.x;
    const int g    = blockIdx.x * 32 + lane;
    if (g >= GG) return;
    const int t0   = blockIdx.y * SLEN;

    // routing params (sigmoid of last row, cols 16..19)
    const float* pr = par + ((size_t)(TT - 1) * GG + g) * 20 + 16;
    float a1 = 0.3f  + (20.0f - 0.3f)  / (1.0f + expf(-__ldg(pr + 0)));
    float b1 = 0.01f + (5.0f  - 0.01f) / (1.0f + expf(-__ldg(pr + 1)));
    float a2 = 0.5f  + (13.0f - 0.5f)  / (1.0f + expf(-__ldg(pr + 2)));
    float b2 = 0.15f + (1.5f  - 0.15f) / (1.0f + expf(-__ldg(pr + 3)));

    unsigned long long uhp[CH];
    {
        const float L2E = 1.44269504f;
        float i1 = L2E / b1, i2 = L2E / b2;
        float w1[CH], w2[CH];
        float n1 = 0.f, n2 = 0.f;
#pragma unroll
        for (int l = 0; l < CH; l++) {
            float t  = (float)l + 0.5f;
            float lt = lg2a(t);
            w1[l] = ex2a(fmaf(a1 - 1.0f, lt, -t * i1));
            w2[l] = ex2a(fmaf(a2 - 1.0f, lt, -t * i2));
            n1 += w1[l]; n2 += w2[l];
        }
        n1 = 1.0f / n1; n2 = 1.0f / n2;
#pragma unroll
        for (int l = 0; l < CH; l++) PACK2(uhp[l], w1[l] * n1, w2[l] * n2);
    }

    // ring preload: slot j holds h[t0 - 15 + j]
    unsigned long long hpk[CH];
    hpk[0] = 0ull;
#pragma unroll
    for (int j = 1; j < CH; j++) {
        int t = t0 - CH + j;
        if (t >= 0) {
            float4 h = __ldg(&g_scr[(size_t)t * GG + g]);
            PACK2(hpk[j], h.x, h.y);
        } else hpk[j] = 0ull;
    }

#pragma unroll 1
    for (int cb = 0; cb < SLEN / CH; cb++) {
        const int tb = t0 + cb * CH;
        if (tb >= TT) break;

        // batch-load 15 history rows (MLP=15)
        float4 hv[CH];
#pragma unroll
        for (int u = 0; u < CH; u++) {
            int t = tb + u;
            hv[u] = (t < TT) ? __ldg(&g_scr[(size_t)t * GG + g])
                             : make_float4(0.f, 0.f, 0.f, 0.f);
        }
#pragma unroll
        for (int u = 0; u < CH; u++) {
            PACK2(hpk[u], hv[u].x, hv[u].y);
            unsigned long long qp = 0ull;
#pragma unroll
            for (int l = 0; l < CH; l++)
                FMA2(qp, uhp[l], hpk[(u - l + CH) % CH], qp);
            float qlo, qhi;
            UNPACK2(qlo, qhi, qp);
            if (tb + u < TT)
                out[(size_t)(tb + u) * GG + g] = hv[u].z + qlo + qhi;
        }
    }
}

extern "C" void kernel_launch(void* const* d_in, const int* in_sizes, int n_in,
                              void* d_out, int out_size)
{
    (void)in_sizes; (void)n_in; (void)out_size;
    const float* x   = (const float*)d_in[0];   // x_phy  [1460, 5000, 3]
    const float* par = (const float*)d_in[1];   // params [1460, 5000, 20]
    float* out = (float*)d_out;                 // Q      [1460, 5000]

    hmets_scan<<<(GG + 31) / 32, 32>>>(x, par);
    dim3 cg((GG + 31) / 32, NSL);
    hmets_conv<<<cg, 32>>>(par, out);
}

// round 9
// speedup vs baseline: 2.0577x; 1.3878x over previous
#include <cuda_runtime.h>
#include <math.h>

#define TT   1460
#define GG   5000
#define TS   30              // timesteps per smem tile (2 x 15-chunk)
#define NT   49              // ceil(1460/30)
#define ROWF 96              // 32 cells * 3 floats per timestep row
#define CH   15              // UH length = ring period

// ---- packed f32x2 + approx transcendental helpers -----------------------------
#define PACK2(d, lo, hi)   asm("mov.b64 %0, {%1, %2};" : "=l"(d) : "f"(lo), "f"(hi))
#define UNPACK2(lo, hi, d) asm("mov.b64 {%0, %1}, %2;" : "=f"(lo), "=f"(hi) : "l"(d))
#define FMA2(d, a, b, c)   asm("fma.rn.f32x2 %0, %1, %2, %3;" : "=l"(d) : "l"(a), "l"(b), "l"(c))

__device__ __forceinline__ float lg2a(float x) { float r; asm("lg2.approx.f32 %0, %1;" : "=f"(r) : "f"(x)); return r; }
__device__ __forceinline__ float ex2a(float x) { float r; asm("ex2.approx.f32 %0, %1;" : "=f"(r) : "f"(x)); return r; }

__device__ __forceinline__ void cp_async16(void* sm, const void* gm) {
    unsigned a = (unsigned)__cvta_generic_to_shared(sm);
    asm volatile("cp.async.cg.shared.global [%0], [%1], 16;\n" :: "r"(a), "l"(gm));
}
__device__ __forceinline__ void cp_commit() { asm volatile("cp.async.commit_group;\n" ::: "memory"); }
__device__ __forceinline__ void cp_wait1()  { asm volatile("cp.async.wait_group 1;\n" ::: "memory"); }
__device__ __forceinline__ void cp_wait0()  { asm volatile("cp.async.wait_group 0;\n" ::: "memory"); }

__global__ __launch_bounds__(32, 1)
void hmets_kernel(const float* __restrict__ x,
                  const float* __restrict__ par,
                  float* __restrict__ out)
{
    __shared__ float sm[2 * TS * ROWF];   // 23040 B double buffered
    const int lane = threadIdx.x;
    const int g0   = blockIdx.x * 32;
    const int g    = g0 + lane;
    const bool active  = (g < GG);
    const bool fullblk = (g0 + 32 <= GG);

    // ---------------- parameters: only the last timestep row is live ----------------
    const float* pr = par + ((size_t)(TT - 1) * GG + (active ? g : (GG - 1))) * 20;
    float s[20];
#pragma unroll
    for (int i = 0; i < 20; i++) {
        float v = __ldg(pr + i);
        s[i] = 1.0f / (1.0f + expf(-v));
    }
    const float ddf_min = 20.0f * s[0];
    const float ddf_sum = ddf_min + 20.0f * s[1];
    const float Tbm     = -2.0f + 5.0f * s[2];
    const float Kcum    = 0.01f + 0.19f * s[3];
    const float fcmin   = 0.1f * s[4];
    const float fc_sum  = fcmin + 0.01f + 0.24f * s[5];
    const float Ccum    = 0.005f + 0.045f * s[6];
    const float Tbf     = -5.0f + 7.0f * s[7];
    const float Kf      = 5.0f * s[8];
    const float efe     = s[9];
    const float ETe     = 3.0f * s[10];
    const float cRun    = s[11];
    const float cV2P    = 1e-5f + (0.02f - 1e-5f) * s[12];
    const float cVad    = 0.1f * s[13];
    const float cPh     = 1e-5f + (0.01f - 1e-5f) * s[14];
    const float Vmax    = 0.001f + (500.0f - 0.001f) * s[15];
    const float invVmax = 1.0f / Vmax;
    // chain-shortening precomputes (off-chain constants)
    const float dmK  = ddf_min * Kcum;       // ddf = fma(dmK, C, ddf_min)
    const float fcC  = fc_sum * Ccum;        // wrf = fma(-fcC, C, fc_sum)
    const float cVb  = 1.0f - cVad - cV2P;   // V1 = fma(cVb, V, infil) - ht1

    // ---------------- gamma unit hydrographs, packed (uh1[l], uh2[l]) ---------------
    unsigned long long uhp[CH];
    {
        float a1 = 0.3f  + (20.0f - 0.3f)  * s[16];
        float b1 = 0.01f + (5.0f  - 0.01f) * s[17];
        float a2 = 0.5f  + (13.0f - 0.5f)  * s[18];
        float b2 = 0.15f + (1.5f  - 0.15f) * s[19];
        float i1 = 1.0f / b1, i2 = 1.0f / b2;
        float w1[CH], w2[CH];
        float n1 = 0.f, n2 = 0.f;
#pragma unroll
        for (int l = 0; l < CH; l++) {
            float t  = (float)l + 0.5f;
            w1[l] = powf(t, a1 - 1.0f) * expf(-t * i1);
            w2[l] = powf(t, a2 - 1.0f) * expf(-t * i2);
            n1 += w1[l]; n2 += w2[l];
        }
        n1 = 1.0f / n1; n2 = 1.0f / n2;
#pragma unroll
        for (int l = 0; l < CH; l++) PACK2(uhp[l], w1[l] * n1, w2[l] * n2);
    }

    // ---------------- tile prefetch (zero-fill beyond TT and for tail cells) --------
    auto prefetch = [&](int k) {
        float* dst = sm + (k & 1) * (TS * ROWF);
        int t0 = k * TS;
        if (fullblk) {
            for (int j = lane; j < TS * 24; j += 32) {       // 24 float4 per row
                int row = j / 24, c = j - row * 24;
                if (t0 + row < TT) {
                    const float* gp = x + (size_t)(t0 + row) * (GG * 3) + g0 * 3 + c * 4;
                    cp_async16(dst + row * ROWF + c * 4, gp);
                } else {
                    float4 z = {0.f, 0.f, 0.f, 0.f};
                    *(float4*)(dst + row * ROWF + c * 4) = z;
                }
            }
        } else {
            for (int j = lane; j < TS * ROWF; j += 32) {
                int row = j / ROWF, c = j - row * ROWF;
                int cell = g0 + c / 3;
                dst[row * ROWF + c] = (cell < GG && t0 + row < TT)
                    ? __ldg(x + (size_t)(t0 + row) * (GG * 3) + g0 * 3 + c) : 0.0f;
            }
        }
        cp_commit();
    };

    // ---------------- state + packed conv history (circular, unroll-aligned) --------
    float S = 1e-5f, W = 1e-5f, C = 1e-5f, P = 1e-5f;
    float V = 0.5f * Vmax;
    unsigned long long hpk[CH];
#pragma unroll
    for (int l = 0; l < CH; l++) hpk[l] = 0ull;

    float* op = out + g;          // advances by GG per step

    prefetch(0);
    for (int k = 0; k < NT; k++) {
        const int t0 = k * TS;
        if (k + 1 < NT) { prefetch(k + 1); cp_wait1(); }
        else            { cp_wait0(); }
        __syncwarp();
        const float* sb = sm + (k & 1) * (TS * ROWF);

#pragma unroll 1
        for (int c2 = 0; c2 < 2; c2++) {        // two aligned 15-chunks per tile
            const float* rb = sb + c2 * CH * ROWF + lane * 3;
            const int tb = t0 + c2 * CH;
#pragma unroll
            for (int u = 0; u < CH; u++) {
                float Pp = rb[u * ROWF + 0];
                float Tt = rb[u * ROWF + 1];
                float PE = rb[u * ROWF + 2];

                // forcing-derived (all off the state recurrence)
                float rain = (Tt >= 0.0f) ? Pp : 0.0f;
                float snow = Pp - rain;
                float base = fmaxf(Tbf - Tt, 1e-5f);
                float potf = Kf * ex2a(efe * lg2a(base));
                float dtp  = fmaxf(Tt - Tbm, 0.0f);   // zero-clamp moved off-chain
                float RET  = ETe * PE;

                // snowpack (shortened chain)
                float fr = fminf(potf, W);
                W -= fr;
                S += fr;
                float ddf  = fminf(fmaf(dmK, C, ddf_min), ddf_sum);
                float S1   = S + snow;
                float melt = fminf(ddf * dtp, S1);
                S = S1 - melt;
                float Ct = C + melt;
                C = (S > 1e-5f) ? Ct : 0.0f;

                // retention: select -> min identity (exact)
                float wrf  = fmaxf(fmaf(-fcC, C, fc_sum), fcmin);
                float wr   = wrf * S;
                float wtmp = (W + rain) + melt;
                float wa   = fmaxf(wtmp - wr, 0.0f);
                W = fminf(wtmp, wr);

                // vadose / phreatic: overflow clamp -> min identity (exact)
                float ratio = V * invVmax;
                float cr    = cRun * ratio;
                float cr2   = cr * ratio;
                float ht0   = cr * wa;
                float infil = fmaxf((wa - RET) - ht0, 0.0f);
                float ht1   = cr2 * infil;
                float ht2   = cVad * V;
                float v2p   = cV2P * V;
                float V1    = fmaf(cVb, V, infil) - ht1;
                V = fminf(V1, Vmax);
                ht1 += V1 - V;
                float Pp1 = P + v2p;
                float ht3 = cPh * Pp1;
                P = Pp1 - ht3;

                // 15-tap dual UH conv: two packed FFMA2 accumulator chains
                PACK2(hpk[u], ht0, ht1);
                unsigned long long qp0 = 0ull, qp1 = 0ull;
#pragma unroll
                for (int l = 0; l < 8; l++)
                    FMA2(qp0, uhp[l], hpk[(u - l + CH) % CH], qp0);
#pragma unroll
                for (int l = 8; l < CH; l++)
                    FMA2(qp1, uhp[l], hpk[(u - l + CH) % CH], qp1);
                float qa, qb, qc, qd;
                UNPACK2(qa, qb, qp0);
                UNPACK2(qc, qd, qp1);
                float q = ((ht2 + ht3) + (qa + qb)) + (qc + qd);

                if (active && (tb + u) < TT) *op = q;
                op += GG;
            }
        }
        __syncwarp();
    }
}

extern "C" void kernel_launch(void* const* d_in, const int* in_sizes, int n_in,
                              void* d_out, int out_size)
{
    (void)in_sizes; (void)n_in; (void)out_size;
    const float* x   = (const float*)d_in[0];   // x_phy  [1460, 5000, 3]
    const float* par = (const float*)d_in[1];   // params [1460, 5000, 20]
    float* out = (float*)d_out;                 // Q      [1460, 5000]
    hmets_kernel<<<(GG + 31) / 32, 32>>>(x, par, out);
}